// round 2
// baseline (speedup 1.0000x reference)
#include <cuda_runtime.h>
#include <cuda_bf16.h>
#include <math.h>

#define B_  2
#define T_  2048
#define D_  2048
#define H_  16
#define G_  4
#define HD_ 128

// ---------------- scratch (static device globals; no allocation) ----------------
__device__ float g_qg[(size_t)B_ * T_ * H_ * 2 * HD_];   // (B,T,H,256): q half + gate half
__device__ float g_q [(size_t)B_ * H_ * T_ * HD_];       // (B,H,T,HD) normed+roped+scaled
__device__ float g_k [(size_t)B_ * T_ * G_ * HD_];       // (B,T,G,HD) normed+roped in place
__device__ float g_v [(size_t)B_ * T_ * G_ * HD_];       // (B,T,G,HD)
__device__ float g_attn[(size_t)B_ * T_ * H_ * HD_];     // (B,T,H*HD) gated attention out

// ---------------- generic fp32 SGEMM: C[M,N] = A[M,K] * B[K,N] ----------------
// 128x128 tile, BK=8, 256 threads, 8x8 per-thread micro-tile.
__global__ void sgemm128(const float* __restrict__ A, const float* __restrict__ Bm,
                         float* __restrict__ C, int M, int N, int K) {
    __shared__ float As[8][128];
    __shared__ float Bs[8][128];

    int bx = blockIdx.x;           // N tile
    int by = blockIdx.y;           // M tile
    int tid = threadIdx.x;         // 256
    int tx = tid & 15, ty = tid >> 4;

    int arow = tid >> 1;           // 0..127
    int acol = (tid & 1) * 4;      // 0 or 4
    int brow = tid >> 5;           // 0..7
    int bcol = (tid & 31) * 4;     // 0..124

    const float* Aptr = A + (size_t)(by * 128 + arow) * K + acol;
    const float* Bptr = Bm + (size_t)brow * N + bx * 128 + bcol;

    float acc[8][8];
#pragma unroll
    for (int i = 0; i < 8; i++)
#pragma unroll
        for (int j = 0; j < 8; j++) acc[i][j] = 0.f;

    for (int k0 = 0; k0 < K; k0 += 8) {
        float4 av = *(const float4*)(Aptr + k0);
        float4 bv = *(const float4*)(Bptr + (size_t)k0 * N);
        As[acol + 0][arow] = av.x;
        As[acol + 1][arow] = av.y;
        As[acol + 2][arow] = av.z;
        As[acol + 3][arow] = av.w;
        *(float4*)&Bs[brow][bcol] = bv;
        __syncthreads();

#pragma unroll
        for (int kk = 0; kk < 8; kk++) {
            float a[8], b[8];
            *(float4*)(a)     = *(float4*)&As[kk][ty * 8];
            *(float4*)(a + 4) = *(float4*)&As[kk][ty * 8 + 4];
            *(float4*)(b)     = *(float4*)&Bs[kk][tx * 8];
            *(float4*)(b + 4) = *(float4*)&Bs[kk][tx * 8 + 4];
#pragma unroll
            for (int i = 0; i < 8; i++)
#pragma unroll
                for (int j = 0; j < 8; j++) acc[i][j] += a[i] * b[j];
        }
        __syncthreads();
    }

#pragma unroll
    for (int i = 0; i < 8; i++) {
        size_t r = (size_t)(by * 128 + ty * 8 + i);
        float* Crow = C + r * N + bx * 128 + tx * 8;
        *(float4*)(Crow)     = make_float4(acc[i][0], acc[i][1], acc[i][2], acc[i][3]);
        *(float4*)(Crow + 4) = make_float4(acc[i][4], acc[i][5], acc[i][6], acc[i][7]);
    }
}

// ---------------- Q: RMSNorm + RoPE + 1/sqrt(HD), (B,T,H,256) -> (B,H,T,HD) ----------------
__global__ void qnorm_rope(const float* __restrict__ qg, float* __restrict__ qout,
                           const float* __restrict__ w, const float* __restrict__ cs,
                           const float* __restrict__ sn) {
    int t = blockIdx.x;
    int bh = blockIdx.y;
    int b = bh >> 4, h = bh & 15;
    int i = threadIdx.x;  // 128

    const float* row = qg + (((size_t)(b * T_ + t) * H_ + h) * 2 * HD_);
    float v = row[i];

    float ss = v * v;
#pragma unroll
    for (int o = 16; o > 0; o >>= 1) ss += __shfl_xor_sync(0xffffffffu, ss, o);
    __shared__ float warpsum[4];
    __shared__ float normed[HD_];
    if ((i & 31) == 0) warpsum[i >> 5] = ss;
    __syncthreads();
    float tot = warpsum[0] + warpsum[1] + warpsum[2] + warpsum[3];
    float rms = rsqrtf(tot * (1.0f / HD_) + 1e-6f);
    float xv = v * rms * w[i];
    normed[i] = xv;
    __syncthreads();
    float rot = (i < 64) ? -normed[i + 64] : normed[i - 64];
    float o = (xv * cs[t * HD_ + i] + rot * sn[t * HD_ + i]) * 0.08838834764831845f;
    qout[(((size_t)(b * H_ + h) * T_) + t) * HD_ + i] = o;
}

// ---------------- K: RMSNorm + RoPE in place on (B,T,G,HD) ----------------
__global__ void knorm_rope(float* __restrict__ kbuf, const float* __restrict__ w,
                           const float* __restrict__ cs, const float* __restrict__ sn) {
    int t = blockIdx.x;
    int bg = blockIdx.y;
    int b = bg >> 2, g = bg & 3;
    int i = threadIdx.x;

    size_t base = ((size_t)(b * T_ + t) * G_ + g) * HD_;
    float v = kbuf[base + i];

    float ss = v * v;
#pragma unroll
    for (int o = 16; o > 0; o >>= 1) ss += __shfl_xor_sync(0xffffffffu, ss, o);
    __shared__ float warpsum[4];
    __shared__ float normed[HD_];
    if ((i & 31) == 0) warpsum[i >> 5] = ss;
    __syncthreads();
    float tot = warpsum[0] + warpsum[1] + warpsum[2] + warpsum[3];
    float rms = rsqrtf(tot * (1.0f / HD_) + 1e-6f);
    float xv = v * rms * w[i];
    normed[i] = xv;
    __syncthreads();
    float rot = (i < 64) ? -normed[i + 64] : normed[i - 64];
    kbuf[base + i] = xv * cs[t * HD_ + i] + rot * sn[t * HD_ + i];
}

// ---------------- causal GQA flash attention (fp32) + sigmoid gate epilogue ----------------
#define BQ 64
#define BKT 64
#define QPITCH 132
#define FLASH_SMEM ((BQ * QPITCH + BKT * QPITCH + BKT * HD_ + BQ * BKT + 3 * BQ) * 4)

__global__ void flash_attn(const float* __restrict__ Q, const float* __restrict__ K,
                           const float* __restrict__ V, const float* __restrict__ qg,
                           float* __restrict__ Oout) {
    extern __shared__ float sm[];
    float* Qs = sm;                    // BQ  x QPITCH
    float* Ks = Qs + BQ * QPITCH;      // BKT x QPITCH
    float* Vs = Ks + BKT * QPITCH;     // BKT x HD
    float* Ss = Vs + BKT * HD_;        // BQ x BKT
    float* rowm = Ss + BQ * BKT;
    float* rowl = rowm + BQ;
    float* ralp = rowl + BQ;

    int qt = gridDim.x - 1 - blockIdx.x;  // heavy tiles first
    int bh = blockIdx.y;
    int b = bh >> 4, h = bh & 15;
    int g = h >> 2;
    int tid = threadIdx.x;   // 256
    int tx = tid & 15, ty = tid >> 4;

    const float* Qbase = Q + (((size_t)(b * H_ + h) * T_) + qt * BQ) * HD_;
    const float* Kbase = K + ((size_t)b * T_ * G_ + g) * HD_;
    const float* Vbase = V + ((size_t)b * T_ * G_ + g) * HD_;

    for (int i = tid; i < BQ * (HD_ / 4); i += 256) {
        int r = i >> 5, c4 = (i & 31) * 4;
        *(float4*)&Qs[r * QPITCH + c4] = *(const float4*)(Qbase + r * HD_ + c4);
    }
    if (tid < BQ) { rowm[tid] = -3e30f; rowl[tid] = 0.f; }

    float Oacc[4][8];
#pragma unroll
    for (int i = 0; i < 4; i++)
#pragma unroll
        for (int jc = 0; jc < 8; jc++) Oacc[i][jc] = 0.f;
    __syncthreads();

    for (int j = 0; j <= qt; j++) {
        const float* Kt = Kbase + (size_t)(j * BKT) * (G_ * HD_);
        const float* Vt = Vbase + (size_t)(j * BKT) * (G_ * HD_);
        for (int i = tid; i < BKT * (HD_ / 4); i += 256) {
            int r = i >> 5, c4 = (i & 31) * 4;
            *(float4*)&Ks[r * QPITCH + c4] = *(const float4*)(Kt + (size_t)r * (G_ * HD_) + c4);
            *(float4*)&Vs[r * HD_ + c4]    = *(const float4*)(Vt + (size_t)r * (G_ * HD_) + c4);
        }
        __syncthreads();

        float s[4][4];
#pragma unroll
        for (int i = 0; i < 4; i++)
#pragma unroll
            for (int jj = 0; jj < 4; jj++) s[i][jj] = 0.f;

#pragma unroll
        for (int d = 0; d < HD_; d += 4) {
            float4 qv[4], kv[4];
#pragma unroll
            for (int i = 0; i < 4; i++) qv[i] = *(float4*)&Qs[(ty + 16 * i) * QPITCH + d];
#pragma unroll
            for (int jj = 0; jj < 4; jj++) kv[jj] = *(float4*)&Ks[(tx + 16 * jj) * QPITCH + d];
#pragma unroll
            for (int i = 0; i < 4; i++)
#pragma unroll
                for (int jj = 0; jj < 4; jj++) {
                    s[i][jj] += qv[i].x * kv[jj].x;
                    s[i][jj] += qv[i].y * kv[jj].y;
                    s[i][jj] += qv[i].z * kv[jj].z;
                    s[i][jj] += qv[i].w * kv[jj].w;
                }
        }

        if (j == qt) {
#pragma unroll
            for (int i = 0; i < 4; i++)
#pragma unroll
                for (int jj = 0; jj < 4; jj++)
                    if ((tx + 16 * jj) > (ty + 16 * i)) s[i][jj] = -3e30f;
        }

#pragma unroll
        for (int i = 0; i < 4; i++)
#pragma unroll
            for (int jj = 0; jj < 4; jj++)
                Ss[(ty + 16 * i) * BKT + tx + 16 * jj] = s[i][jj];
        __syncthreads();

        if (tid < BQ) {
            float* Sr = &Ss[tid * BKT];
            float m = rowm[tid], mn = m;
#pragma unroll 8
            for (int c = 0; c < BKT; c++) mn = fmaxf(mn, Sr[c]);
            float a = __expf(m - mn);
            float l = rowl[tid] * a;
#pragma unroll 8
            for (int c = 0; c < BKT; c++) { float p = __expf(Sr[c] - mn); Sr[c] = p; l += p; }
            rowm[tid] = mn; rowl[tid] = l; ralp[tid] = a;
        }
        __syncthreads();

        float a4[4];
#pragma unroll
        for (int i = 0; i < 4; i++) a4[i] = ralp[ty + 16 * i];
#pragma unroll
        for (int i = 0; i < 4; i++)
#pragma unroll
            for (int jc = 0; jc < 8; jc++) Oacc[i][jc] *= a4[i];

#pragma unroll 8
        for (int kk = 0; kk < BKT; kk++) {
            float4 v0 = *(float4*)&Vs[kk * HD_ + tx * 8];
            float4 v1 = *(float4*)&Vs[kk * HD_ + tx * 8 + 4];
#pragma unroll
            for (int i = 0; i < 4; i++) {
                float p = Ss[(ty + 16 * i) * BKT + kk];
                Oacc[i][0] += p * v0.x; Oacc[i][1] += p * v0.y;
                Oacc[i][2] += p * v0.z; Oacc[i][3] += p * v0.w;
                Oacc[i][4] += p * v1.x; Oacc[i][5] += p * v1.y;
                Oacc[i][6] += p * v1.z; Oacc[i][7] += p * v1.w;
            }
        }
        __syncthreads();
    }

    // epilogue: 1/l normalization + sigmoid gate
#pragma unroll
    for (int i = 0; i < 4; i++) {
        int r = ty + 16 * i;
        float linv = 1.0f / rowl[r];
        int grow = qt * BQ + r;
        const float* gptr = qg + (((size_t)(b * T_ + grow) * H_ + h) * 2 * HD_) + HD_ + tx * 8;
        float* optr = Oout + ((size_t)(b * T_ + grow) * (H_ * HD_)) + h * HD_ + tx * 8;
#pragma unroll
        for (int jc = 0; jc < 8; jc++) {
            float gt = gptr[jc];
            float sg = 1.0f / (1.0f + __expf(-gt));
            optr[jc] = Oacc[i][jc] * linv * sg;
        }
    }
}

// ---------------- launch ----------------
extern "C" void kernel_launch(void* const* d_in, const int* in_sizes, int n_in,
                              void* d_out, int out_size) {
    const float* x    = (const float*)d_in[0];
    const float* w_q  = (const float*)d_in[1];
    const float* w_k  = (const float*)d_in[2];
    const float* w_v  = (const float*)d_in[3];
    const float* w_o  = (const float*)d_in[4];
    const float* qnw  = (const float*)d_in[5];
    const float* knw  = (const float*)d_in[6];
    const float* cs   = (const float*)d_in[7];
    const float* sn   = (const float*)d_in[8];
    float* out = (float*)d_out;

    float *qg, *q, *k, *v, *attn;
    cudaGetSymbolAddress((void**)&qg,   g_qg);
    cudaGetSymbolAddress((void**)&q,    g_q);
    cudaGetSymbolAddress((void**)&k,    g_k);
    cudaGetSymbolAddress((void**)&v,    g_v);
    cudaGetSymbolAddress((void**)&attn, g_attn);

    cudaFuncSetAttribute((const void*)flash_attn,
                         cudaFuncAttributeMaxDynamicSharedMemorySize, FLASH_SMEM);

    const int M = B_ * T_;  // 4096

    // QKV projections
    sgemm128<<<dim3((2 * H_ * HD_) / 128, M / 128), 256>>>(x, w_q, qg, M, 2 * H_ * HD_, D_);
    sgemm128<<<dim3((G_ * HD_) / 128,     M / 128), 256>>>(x, w_k, k,  M, G_ * HD_,     D_);
    sgemm128<<<dim3((G_ * HD_) / 128,     M / 128), 256>>>(x, w_v, v,  M, G_ * HD_,     D_);

    // norms + rope
    qnorm_rope<<<dim3(T_, B_ * H_), 128>>>(qg, q, qnw, cs, sn);
    knorm_rope<<<dim3(T_, B_ * G_), 128>>>(k, knw, cs, sn);

    // attention + gate
    flash_attn<<<dim3(T_ / BQ, B_ * H_), 256, FLASH_SMEM>>>(q, k, v, qg, attn);

    // output projection
    sgemm128<<<dim3(D_ / 128, M / 128), 256>>>(attn, w_o, out, M, D_, D_);
}

// round 3
// speedup vs baseline: 1.2405x; 1.2405x over previous
#include <cuda_runtime.h>
#include <cuda_bf16.h>
#include <math.h>

#define B_  2
#define T_  2048
#define D_  2048
#define H_  16
#define G_  4
#define HD_ 128

// ---------------- scratch (static device globals; no allocation) ----------------
__device__ float g_qg[(size_t)B_ * T_ * H_ * 2 * HD_];   // (B,T,H,256): q half + gate half
__device__ float g_q [(size_t)B_ * H_ * T_ * HD_];       // (B,H,T,HD) normed+roped+scaled
__device__ float g_k [(size_t)B_ * T_ * G_ * HD_];       // (B,T,G,HD) normed+roped in place
__device__ float g_v [(size_t)B_ * T_ * G_ * HD_];       // (B,T,G,HD)
__device__ float g_attn[(size_t)B_ * T_ * H_ * HD_];     // (B,T,H*HD) gated attn, tf32-rounded
// tf32-rounded copies (bit patterns stored as float)
__device__ float g_xt [(size_t)B_ * T_ * D_];
__device__ float g_wqt[(size_t)D_ * 2 * H_ * HD_];
__device__ float g_wkt[(size_t)D_ * G_ * HD_];
__device__ float g_wvt[(size_t)D_ * G_ * HD_];
__device__ float g_wot[(size_t)H_ * HD_ * D_];

// ---------------- tf32 round-to-nearest conversion (vectorized) ----------------
__device__ __forceinline__ unsigned f2tf32(float x) {
    unsigned r;
    asm("cvt.rna.tf32.f32 %0, %1;" : "=r"(r) : "f"(x));
    return r;
}

__global__ void cvt_tf32(const float* __restrict__ in, float* __restrict__ out, int n4) {
    int i = blockIdx.x * blockDim.x + threadIdx.x;
    if (i < n4) {
        float4 v = ((const float4*)in)[i];
        uint4 o;
        o.x = f2tf32(v.x); o.y = f2tf32(v.y); o.z = f2tf32(v.z); o.w = f2tf32(v.w);
        ((uint4*)out)[i] = o;
    }
}

// ---------------- tf32 tensor-core GEMM: C[M,N] = A[M,K] * B[K,N] ----------------
// A, B hold tf32 bit patterns. 128x128x16 tile, 256 threads (8 warps, 64x32 warp tile),
// cp.async double buffering. Conflict-free smem pitches: A pitch 20, B pitch 136.
#define APITCH 20
#define BPITCH 136

__device__ __forceinline__ void cp16(float* smem_dst, const float* gsrc) {
    unsigned sa = (unsigned)__cvta_generic_to_shared(smem_dst);
    asm volatile("cp.async.cg.shared.global [%0], [%1], 16;\n" :: "r"(sa), "l"(gsrc));
}

__global__ __launch_bounds__(256, 2) void gemm_tf32(
        const float* __restrict__ A, const float* __restrict__ Bm,
        float* __restrict__ C, int M, int N, int K) {
    __shared__ float As[2][128 * APITCH];
    __shared__ float Bs[2][16 * BPITCH];

    int tid  = threadIdx.x;
    int lane = tid & 31;
    int warp = tid >> 5;
    int wm = (warp & 1) * 64;   // warp M offset within tile
    int wn = (warp >> 1) * 32;  // warp N offset within tile
    int bx = blockIdx.x, by = blockIdx.y;

    const float* Ab = A + (size_t)by * 128 * K;
    const float* Bb = Bm + (size_t)bx * 128;

    // cp.async assignments: A = 128 rows x 4 chunks(16B); B = 16 rows x 32 chunks
    int ar0 = tid >> 1,          akc0 = (tid & 1) * 2;      // chunks tid*2: row=tid/2? no: see below
    // A: chunk ids c and c+256 with c = tid: row=c>>2, kc=c&3
    int a0row = tid >> 2,          a0kc = tid & 3;
    int a1row = (tid + 256) >> 2,  a1kc = tid & 3;
    // B: chunk ids tid, tid+256: row=c>>5, nc=c&31
    int b0row = tid >> 5,          b0nc = tid & 31;
    int b1row = (tid + 256) >> 5,  b1nc = tid & 31;
    (void)ar0; (void)akc0;

    float acc[4][4][4];
#pragma unroll
    for (int i = 0; i < 4; i++)
#pragma unroll
        for (int j = 0; j < 4; j++)
#pragma unroll
            for (int c = 0; c < 4; c++) acc[i][j][c] = 0.f;

    int nk = K / 16;

    // prologue: load tile 0 into buf 0
    {
        cp16(&As[0][a0row * APITCH + a0kc * 4], Ab + (size_t)a0row * K + a0kc * 4);
        cp16(&As[0][a1row * APITCH + a1kc * 4], Ab + (size_t)a1row * K + a1kc * 4);
        cp16(&Bs[0][b0row * BPITCH + b0nc * 4], Bb + (size_t)b0row * N + b0nc * 4);
        cp16(&Bs[0][b1row * BPITCH + b1nc * 4], Bb + (size_t)b1row * N + b1nc * 4);
        asm volatile("cp.async.commit_group;\n");
    }

    int buf = 0;
    for (int kt = 0; kt < nk; kt++) {
        asm volatile("cp.async.wait_group 0;\n");
        __syncthreads();

        if (kt + 1 < nk) {
            int kb = (kt + 1) * 16;
            int nb = buf ^ 1;
            cp16(&As[nb][a0row * APITCH + a0kc * 4], Ab + (size_t)a0row * K + kb + a0kc * 4);
            cp16(&As[nb][a1row * APITCH + a1kc * 4], Ab + (size_t)a1row * K + kb + a1kc * 4);
            cp16(&Bs[nb][b0row * BPITCH + b0nc * 4], Bb + (size_t)(kb + b0row) * N + b0nc * 4);
            cp16(&Bs[nb][b1row * BPITCH + b1nc * 4], Bb + (size_t)(kb + b1row) * N + b1nc * 4);
        }
        asm volatile("cp.async.commit_group;\n");

        const float* Asb = As[buf];
        const float* Bsb = Bs[buf];
        int r  = lane >> 2;
        int kc = lane & 3;
#pragma unroll
        for (int ks = 0; ks < 2; ks++) {
            int k0 = ks * 8;
            unsigned af[4][4];
#pragma unroll
            for (int mf = 0; mf < 4; mf++) {
                int m = wm + mf * 16;
                af[mf][0] = __float_as_uint(Asb[(m + r)     * APITCH + k0 + kc]);
                af[mf][1] = __float_as_uint(Asb[(m + r + 8) * APITCH + k0 + kc]);
                af[mf][2] = __float_as_uint(Asb[(m + r)     * APITCH + k0 + kc + 4]);
                af[mf][3] = __float_as_uint(Asb[(m + r + 8) * APITCH + k0 + kc + 4]);
            }
            unsigned bf[4][2];
#pragma unroll
            for (int nf = 0; nf < 4; nf++) {
                int n = wn + nf * 8;
                bf[nf][0] = __float_as_uint(Bsb[(k0 + kc)     * BPITCH + n + r]);
                bf[nf][1] = __float_as_uint(Bsb[(k0 + kc + 4) * BPITCH + n + r]);
            }
#pragma unroll
            for (int mf = 0; mf < 4; mf++)
#pragma unroll
                for (int nf = 0; nf < 4; nf++) {
                    asm volatile(
                        "mma.sync.aligned.m16n8k8.row.col.f32.tf32.tf32.f32 "
                        "{%0,%1,%2,%3}, {%4,%5,%6,%7}, {%8,%9}, {%0,%1,%2,%3};\n"
                        : "+f"(acc[mf][nf][0]), "+f"(acc[mf][nf][1]),
                          "+f"(acc[mf][nf][2]), "+f"(acc[mf][nf][3])
                        : "r"(af[mf][0]), "r"(af[mf][1]), "r"(af[mf][2]), "r"(af[mf][3]),
                          "r"(bf[nf][0]), "r"(bf[nf][1]));
                }
        }
        buf ^= 1;
    }

    // epilogue
    int r  = lane >> 2;
    int cc = (lane & 3) * 2;
#pragma unroll
    for (int mf = 0; mf < 4; mf++) {
#pragma unroll
        for (int nf = 0; nf < 4; nf++) {
            size_t row0 = (size_t)(by * 128 + wm + mf * 16 + r);
            int col = bx * 128 + wn + nf * 8 + cc;
            *(float2*)&C[row0 * N + col]       = make_float2(acc[mf][nf][0], acc[mf][nf][1]);
            *(float2*)&C[(row0 + 8) * N + col] = make_float2(acc[mf][nf][2], acc[mf][nf][3]);
        }
    }
}

// ---------------- Q: RMSNorm + RoPE + 1/sqrt(HD), (B,T,H,256) -> (B,H,T,HD) ----------------
__global__ void qnorm_rope(const float* __restrict__ qg, float* __restrict__ qout,
                           const float* __restrict__ w, const float* __restrict__ cs,
                           const float* __restrict__ sn) {
    int t = blockIdx.x;
    int bh = blockIdx.y;
    int b = bh >> 4, h = bh & 15;
    int i = threadIdx.x;  // 128

    const float* row = qg + (((size_t)(b * T_ + t) * H_ + h) * 2 * HD_);
    float v = row[i];

    float ss = v * v;
#pragma unroll
    for (int o = 16; o > 0; o >>= 1) ss += __shfl_xor_sync(0xffffffffu, ss, o);
    __shared__ float warpsum[4];
    __shared__ float normed[HD_];
    if ((i & 31) == 0) warpsum[i >> 5] = ss;
    __syncthreads();
    float tot = warpsum[0] + warpsum[1] + warpsum[2] + warpsum[3];
    float rms = rsqrtf(tot * (1.0f / HD_) + 1e-6f);
    float xv = v * rms * w[i];
    normed[i] = xv;
    __syncthreads();
    float rot = (i < 64) ? -normed[i + 64] : normed[i - 64];
    float o = (xv * cs[t * HD_ + i] + rot * sn[t * HD_ + i]) * 0.08838834764831845f;
    qout[(((size_t)(b * H_ + h) * T_) + t) * HD_ + i] = o;
}

// ---------------- K: RMSNorm + RoPE in place on (B,T,G,HD) ----------------
__global__ void knorm_rope(float* __restrict__ kbuf, const float* __restrict__ w,
                           const float* __restrict__ cs, const float* __restrict__ sn) {
    int t = blockIdx.x;
    int bg = blockIdx.y;
    int b = bg >> 2, g = bg & 3;
    int i = threadIdx.x;

    size_t base = ((size_t)(b * T_ + t) * G_ + g) * HD_;
    float v = kbuf[base + i];

    float ss = v * v;
#pragma unroll
    for (int o = 16; o > 0; o >>= 1) ss += __shfl_xor_sync(0xffffffffu, ss, o);
    __shared__ float warpsum[4];
    __shared__ float normed[HD_];
    if ((i & 31) == 0) warpsum[i >> 5] = ss;
    __syncthreads();
    float tot = warpsum[0] + warpsum[1] + warpsum[2] + warpsum[3];
    float rms = rsqrtf(tot * (1.0f / HD_) + 1e-6f);
    float xv = v * rms * w[i];
    normed[i] = xv;
    __syncthreads();
    float rot = (i < 64) ? -normed[i + 64] : normed[i - 64];
    kbuf[base + i] = xv * cs[t * HD_ + i] + rot * sn[t * HD_ + i];
}

// ---------------- causal GQA flash attention (fp32) + sigmoid gate epilogue ----------------
#define BQ 64
#define BKT 64
#define QPITCH 132
#define FLASH_SMEM ((BQ * QPITCH + BKT * QPITCH + BKT * HD_ + BQ * BKT + 3 * BQ) * 4)

__global__ void flash_attn(const float* __restrict__ Q, const float* __restrict__ K,
                           const float* __restrict__ V, const float* __restrict__ qg,
                           float* __restrict__ Oout) {
    extern __shared__ float sm[];
    float* Qs = sm;                    // BQ  x QPITCH
    float* Ks = Qs + BQ * QPITCH;      // BKT x QPITCH
    float* Vs = Ks + BKT * QPITCH;     // BKT x HD
    float* Ss = Vs + BKT * HD_;        // BQ x BKT
    float* rowm = Ss + BQ * BKT;
    float* rowl = rowm + BQ;
    float* ralp = rowl + BQ;

    int qt = gridDim.x - 1 - blockIdx.x;  // heavy tiles first
    int bh = blockIdx.y;
    int b = bh >> 4, h = bh & 15;
    int g = h >> 2;
    int tid = threadIdx.x;   // 256
    int tx = tid & 15, ty = tid >> 4;

    const float* Qbase = Q + (((size_t)(b * H_ + h) * T_) + qt * BQ) * HD_;
    const float* Kbase = K + ((size_t)b * T_ * G_ + g) * HD_;
    const float* Vbase = V + ((size_t)b * T_ * G_ + g) * HD_;

    for (int i = tid; i < BQ * (HD_ / 4); i += 256) {
        int r = i >> 5, c4 = (i & 31) * 4;
        *(float4*)&Qs[r * QPITCH + c4] = *(const float4*)(Qbase + r * HD_ + c4);
    }
    if (tid < BQ) { rowm[tid] = -3e30f; rowl[tid] = 0.f; }

    float Oacc[4][8];
#pragma unroll
    for (int i = 0; i < 4; i++)
#pragma unroll
        for (int jc = 0; jc < 8; jc++) Oacc[i][jc] = 0.f;
    __syncthreads();

    for (int j = 0; j <= qt; j++) {
        const float* Kt = Kbase + (size_t)(j * BKT) * (G_ * HD_);
        const float* Vt = Vbase + (size_t)(j * BKT) * (G_ * HD_);
        for (int i = tid; i < BKT * (HD_ / 4); i += 256) {
            int r = i >> 5, c4 = (i & 31) * 4;
            *(float4*)&Ks[r * QPITCH + c4] = *(const float4*)(Kt + (size_t)r * (G_ * HD_) + c4);
            *(float4*)&Vs[r * HD_ + c4]    = *(const float4*)(Vt + (size_t)r * (G_ * HD_) + c4);
        }
        __syncthreads();

        float s[4][4];
#pragma unroll
        for (int i = 0; i < 4; i++)
#pragma unroll
            for (int jj = 0; jj < 4; jj++) s[i][jj] = 0.f;

#pragma unroll
        for (int d = 0; d < HD_; d += 4) {
            float4 qv[4], kv[4];
#pragma unroll
            for (int i = 0; i < 4; i++) qv[i] = *(float4*)&Qs[(ty + 16 * i) * QPITCH + d];
#pragma unroll
            for (int jj = 0; jj < 4; jj++) kv[jj] = *(float4*)&Ks[(tx + 16 * jj) * QPITCH + d];
#pragma unroll
            for (int i = 0; i < 4; i++)
#pragma unroll
                for (int jj = 0; jj < 4; jj++) {
                    s[i][jj] += qv[i].x * kv[jj].x;
                    s[i][jj] += qv[i].y * kv[jj].y;
                    s[i][jj] += qv[i].z * kv[jj].z;
                    s[i][jj] += qv[i].w * kv[jj].w;
                }
        }

        if (j == qt) {
#pragma unroll
            for (int i = 0; i < 4; i++)
#pragma unroll
                for (int jj = 0; jj < 4; jj++)
                    if ((tx + 16 * jj) > (ty + 16 * i)) s[i][jj] = -3e30f;
        }

#pragma unroll
        for (int i = 0; i < 4; i++)
#pragma unroll
            for (int jj = 0; jj < 4; jj++)
                Ss[(ty + 16 * i) * BKT + tx + 16 * jj] = s[i][jj];
        __syncthreads();

        if (tid < BQ) {
            float* Sr = &Ss[tid * BKT];
            float m = rowm[tid], mn = m;
#pragma unroll 8
            for (int c = 0; c < BKT; c++) mn = fmaxf(mn, Sr[c]);
            float a = __expf(m - mn);
            float l = rowl[tid] * a;
#pragma unroll 8
            for (int c = 0; c < BKT; c++) { float p = __expf(Sr[c] - mn); Sr[c] = p; l += p; }
            rowm[tid] = mn; rowl[tid] = l; ralp[tid] = a;
        }
        __syncthreads();

        float a4[4];
#pragma unroll
        for (int i = 0; i < 4; i++) a4[i] = ralp[ty + 16 * i];
#pragma unroll
        for (int i = 0; i < 4; i++)
#pragma unroll
            for (int jc = 0; jc < 8; jc++) Oacc[i][jc] *= a4[i];

#pragma unroll 8
        for (int kk = 0; kk < BKT; kk++) {
            float4 v0 = *(float4*)&Vs[kk * HD_ + tx * 8];
            float4 v1 = *(float4*)&Vs[kk * HD_ + tx * 8 + 4];
#pragma unroll
            for (int i = 0; i < 4; i++) {
                float p = Ss[(ty + 16 * i) * BKT + kk];
                Oacc[i][0] += p * v0.x; Oacc[i][1] += p * v0.y;
                Oacc[i][2] += p * v0.z; Oacc[i][3] += p * v0.w;
                Oacc[i][4] += p * v1.x; Oacc[i][5] += p * v1.y;
                Oacc[i][6] += p * v1.z; Oacc[i][7] += p * v1.w;
            }
        }
        __syncthreads();
    }

    // epilogue: 1/l normalization + sigmoid gate + tf32 rounding (feeds w_o tensor GEMM)
#pragma unroll
    for (int i = 0; i < 4; i++) {
        int r = ty + 16 * i;
        float linv = 1.0f / rowl[r];
        int grow = qt * BQ + r;
        const float* gptr = qg + (((size_t)(b * T_ + grow) * H_ + h) * 2 * HD_) + HD_ + tx * 8;
        float* optr = Oout + ((size_t)(b * T_ + grow) * (H_ * HD_)) + h * HD_ + tx * 8;
#pragma unroll
        for (int jc = 0; jc < 8; jc++) {
            float gt = gptr[jc];
            float sg = 1.0f / (1.0f + __expf(-gt));
            float val = Oacc[i][jc] * linv * sg;
            ((unsigned*)optr)[jc] = f2tf32(val);
        }
    }
}

// ---------------- launch ----------------
extern "C" void kernel_launch(void* const* d_in, const int* in_sizes, int n_in,
                              void* d_out, int out_size) {
    const float* x    = (const float*)d_in[0];
    const float* w_q  = (const float*)d_in[1];
    const float* w_k  = (const float*)d_in[2];
    const float* w_v  = (const float*)d_in[3];
    const float* w_o  = (const float*)d_in[4];
    const float* qnw  = (const float*)d_in[5];
    const float* knw  = (const float*)d_in[6];
    const float* cs   = (const float*)d_in[7];
    const float* sn   = (const float*)d_in[8];
    float* out = (float*)d_out;

    float *qg, *q, *k, *v, *attn, *xt, *wqt, *wkt, *wvt, *wot;
    cudaGetSymbolAddress((void**)&qg,   g_qg);
    cudaGetSymbolAddress((void**)&q,    g_q);
    cudaGetSymbolAddress((void**)&k,    g_k);
    cudaGetSymbolAddress((void**)&v,    g_v);
    cudaGetSymbolAddress((void**)&attn, g_attn);
    cudaGetSymbolAddress((void**)&xt,   g_xt);
    cudaGetSymbolAddress((void**)&wqt,  g_wqt);
    cudaGetSymbolAddress((void**)&wkt,  g_wkt);
    cudaGetSymbolAddress((void**)&wvt,  g_wvt);
    cudaGetSymbolAddress((void**)&wot,  g_wot);

    cudaFuncSetAttribute((const void*)flash_attn,
                         cudaFuncAttributeMaxDynamicSharedMemorySize, FLASH_SMEM);

    const int M = B_ * T_;  // 4096

    // tf32 rounding pre-pass
    {
        int n4;
        n4 = (B_ * T_ * D_) / 4;          cvt_tf32<<<(n4 + 255) / 256, 256>>>(x,   xt,  n4);
        n4 = (D_ * 2 * H_ * HD_) / 4;     cvt_tf32<<<(n4 + 255) / 256, 256>>>(w_q, wqt, n4);
        n4 = (D_ * G_ * HD_) / 4;         cvt_tf32<<<(n4 + 255) / 256, 256>>>(w_k, wkt, n4);
        n4 = (D_ * G_ * HD_) / 4;         cvt_tf32<<<(n4 + 255) / 256, 256>>>(w_v, wvt, n4);
        n4 = (H_ * HD_ * D_) / 4;         cvt_tf32<<<(n4 + 255) / 256, 256>>>(w_o, wot, n4);
    }

    // QKV projections (tensor cores, tf32)
    gemm_tf32<<<dim3((2 * H_ * HD_) / 128, M / 128), 256>>>(xt, wqt, qg, M, 2 * H_ * HD_, D_);
    gemm_tf32<<<dim3((G_ * HD_) / 128,     M / 128), 256>>>(xt, wkt, k,  M, G_ * HD_,     D_);
    gemm_tf32<<<dim3((G_ * HD_) / 128,     M / 128), 256>>>(xt, wvt, v,  M, G_ * HD_,     D_);

    // norms + rope
    qnorm_rope<<<dim3(T_, B_ * H_), 128>>>(qg, q, qnw, cs, sn);
    knorm_rope<<<dim3(T_, B_ * G_), 128>>>(k, knw, cs, sn);

    // attention + gate (fp32 SIMT; epilogue emits tf32-rounded attn)
    flash_attn<<<dim3(T_ / BQ, B_ * H_), 256, FLASH_SMEM>>>(q, k, v, qg, attn);

    // output projection (tensor cores, tf32)
    gemm_tf32<<<dim3(D_ / 128, M / 128), 256>>>(attn, wot, out, M, D_, D_);
}

// round 11
// speedup vs baseline: 2.3152x; 1.8664x over previous
#include <cuda_runtime.h>
#include <cuda_bf16.h>
#include <math.h>
#include <stdint.h>

#define B_  2
#define T_  2048
#define D_  2048
#define H_  16
#define G_  4
#define HD_ 128

// ---------------- scratch (static device globals; no allocation) ----------------
__device__ float g_qg[(size_t)B_ * T_ * H_ * 2 * HD_];   // (B,T,H,256): q half + gate half
__device__ float g_q [(size_t)B_ * H_ * T_ * HD_];       // (B,H,T,HD) tf32 bits, normed+roped+scaled
__device__ float g_k [(size_t)B_ * T_ * G_ * HD_];       // (B,T,G,HD) tf32 bits, normed+roped
__device__ float g_v [(size_t)B_ * T_ * G_ * HD_];       // (B,T,G,HD) -> tf32 bits after cvt
__device__ float g_attn[(size_t)B_ * T_ * H_ * HD_];     // (B,T,H*HD) gated attn, tf32 bits
// tf32-rounded copies (bit patterns stored as float)
__device__ float g_xt [(size_t)B_ * T_ * D_];
__device__ float g_wqt[(size_t)D_ * 2 * H_ * HD_];
__device__ float g_wkt[(size_t)D_ * G_ * HD_];
__device__ float g_wvt[(size_t)D_ * G_ * HD_];
__device__ float g_wot[(size_t)H_ * HD_ * D_];

// ---------------- tf32 helpers ----------------
__device__ __forceinline__ unsigned f2tf32(float x) {
    unsigned r;
    asm("cvt.rna.tf32.f32 %0, %1;" : "=r"(r) : "f"(x));
    return r;
}

__device__ __forceinline__ void mma_tf32(float* c, unsigned a0, unsigned a1, unsigned a2,
                                         unsigned a3, unsigned b0, unsigned b1) {
    asm volatile(
        "mma.sync.aligned.m16n8k8.row.col.f32.tf32.tf32.f32 "
        "{%0,%1,%2,%3}, {%4,%5,%6,%7}, {%8,%9}, {%0,%1,%2,%3};\n"
        : "+f"(c[0]), "+f"(c[1]), "+f"(c[2]), "+f"(c[3])
        : "r"(a0), "r"(a1), "r"(a2), "r"(a3), "r"(b0), "r"(b1));
}

__global__ void cvt_tf32(const float* __restrict__ in, float* __restrict__ out, int n4) {
    int i = blockIdx.x * blockDim.x + threadIdx.x;
    if (i < n4) {
        float4 v = ((const float4*)in)[i];
        uint4 o;
        o.x = f2tf32(v.x); o.y = f2tf32(v.y); o.z = f2tf32(v.z); o.w = f2tf32(v.w);
        ((uint4*)out)[i] = o;
    }
}

// ---------------- tf32 tensor-core GEMM (unchanged from R3, passing) ----------------
#define APITCH 20
#define BPITCH 136

__device__ __forceinline__ void cp16(float* smem_dst, const float* gsrc) {
    unsigned sa = (unsigned)__cvta_generic_to_shared(smem_dst);
    asm volatile("cp.async.cg.shared.global [%0], [%1], 16;\n" :: "r"(sa), "l"(gsrc));
}

__global__ __launch_bounds__(256, 2) void gemm_tf32(
        const float* __restrict__ A, const float* __restrict__ Bm,
        float* __restrict__ C, int M, int N, int K) {
    __shared__ float As[2][128 * APITCH];
    __shared__ float Bs[2][16 * BPITCH];

    int tid  = threadIdx.x;
    int lane = tid & 31;
    int warp = tid >> 5;
    int wm = (warp & 1) * 64;
    int wn = (warp >> 1) * 32;
    int bx = blockIdx.x, by = blockIdx.y;

    const float* Ab = A + (size_t)by * 128 * K;
    const float* Bb = Bm + (size_t)bx * 128;

    int a0row = tid >> 2,          a0kc = tid & 3;
    int a1row = (tid + 256) >> 2,  a1kc = tid & 3;
    int b0row = tid >> 5,          b0nc = tid & 31;
    int b1row = (tid + 256) >> 5,  b1nc = tid & 31;

    float acc[4][4][4];
#pragma unroll
    for (int i = 0; i < 4; i++)
#pragma unroll
        for (int j = 0; j < 4; j++)
#pragma unroll
            for (int c = 0; c < 4; c++) acc[i][j][c] = 0.f;

    int nk = K / 16;

    {
        cp16(&As[0][a0row * APITCH + a0kc * 4], Ab + (size_t)a0row * K + a0kc * 4);
        cp16(&As[0][a1row * APITCH + a1kc * 4], Ab + (size_t)a1row * K + a1kc * 4);
        cp16(&Bs[0][b0row * BPITCH + b0nc * 4], Bb + (size_t)b0row * N + b0nc * 4);
        cp16(&Bs[0][b1row * BPITCH + b1nc * 4], Bb + (size_t)b1row * N + b1nc * 4);
        asm volatile("cp.async.commit_group;\n");
    }

    int buf = 0;
    for (int kt = 0; kt < nk; kt++) {
        asm volatile("cp.async.wait_group 0;\n");
        __syncthreads();

        if (kt + 1 < nk) {
            int kb = (kt + 1) * 16;
            int nb = buf ^ 1;
            cp16(&As[nb][a0row * APITCH + a0kc * 4], Ab + (size_t)a0row * K + kb + a0kc * 4);
            cp16(&As[nb][a1row * APITCH + a1kc * 4], Ab + (size_t)a1row * K + kb + a1kc * 4);
            cp16(&Bs[nb][b0row * BPITCH + b0nc * 4], Bb + (size_t)(kb + b0row) * N + b0nc * 4);
            cp16(&Bs[nb][b1row * BPITCH + b1nc * 4], Bb + (size_t)(kb + b1row) * N + b1nc * 4);
        }
        asm volatile("cp.async.commit_group;\n");

        const float* Asb = As[buf];
        const float* Bsb = Bs[buf];
        int r  = lane >> 2;
        int kc = lane & 3;
#pragma unroll
        for (int ks = 0; ks < 2; ks++) {
            int k0 = ks * 8;
            unsigned af[4][4];
#pragma unroll
            for (int mf = 0; mf < 4; mf++) {
                int m = wm + mf * 16;
                af[mf][0] = __float_as_uint(Asb[(m + r)     * APITCH + k0 + kc]);
                af[mf][1] = __float_as_uint(Asb[(m + r + 8) * APITCH + k0 + kc]);
                af[mf][2] = __float_as_uint(Asb[(m + r)     * APITCH + k0 + kc + 4]);
                af[mf][3] = __float_as_uint(Asb[(m + r + 8) * APITCH + k0 + kc + 4]);
            }
            unsigned bf[4][2];
#pragma unroll
            for (int nf = 0; nf < 4; nf++) {
                int n = wn + nf * 8;
                bf[nf][0] = __float_as_uint(Bsb[(k0 + kc)     * BPITCH + n + r]);
                bf[nf][1] = __float_as_uint(Bsb[(k0 + kc + 4) * BPITCH + n + r]);
            }
#pragma unroll
            for (int mf = 0; mf < 4; mf++)
#pragma unroll
                for (int nf = 0; nf < 4; nf++)
                    mma_tf32(acc[mf][nf], af[mf][0], af[mf][1], af[mf][2], af[mf][3],
                             bf[nf][0], bf[nf][1]);
        }
        buf ^= 1;
    }

    int r  = lane >> 2;
    int cc = (lane & 3) * 2;
#pragma unroll
    for (int mf = 0; mf < 4; mf++) {
#pragma unroll
        for (int nf = 0; nf < 4; nf++) {
            size_t row0 = (size_t)(by * 128 + wm + mf * 16 + r);
            int col = bx * 128 + wn + nf * 8 + cc;
            *(float2*)&C[row0 * N + col]       = make_float2(acc[mf][nf][0], acc[mf][nf][1]);
            *(float2*)&C[(row0 + 8) * N + col] = make_float2(acc[mf][nf][2], acc[mf][nf][3]);
        }
    }
}

// ---------------- Q: RMSNorm + RoPE + scale -> tf32 bits, (B,T,H,256) -> (B,H,T,HD) ----------------
__global__ void qnorm_rope(const float* __restrict__ qg, float* __restrict__ qout,
                           const float* __restrict__ w, const float* __restrict__ cs,
                           const float* __restrict__ sn) {
    int t = blockIdx.x;
    int bh = blockIdx.y;
    int b = bh >> 4, h = bh & 15;
    int i = threadIdx.x;  // 128

    const float* row = qg + (((size_t)(b * T_ + t) * H_ + h) * 2 * HD_);
    float v = row[i];

    float ss = v * v;
#pragma unroll
    for (int o = 16; o > 0; o >>= 1) ss += __shfl_xor_sync(0xffffffffu, ss, o);
    __shared__ float warpsum[4];
    __shared__ float normed[HD_];
    if ((i & 31) == 0) warpsum[i >> 5] = ss;
    __syncthreads();
    float tot = warpsum[0] + warpsum[1] + warpsum[2] + warpsum[3];
    float rms = rsqrtf(tot * (1.0f / HD_) + 1e-6f);
    float xv = v * rms * w[i];
    normed[i] = xv;
    __syncthreads();
    float rot = (i < 64) ? -normed[i + 64] : normed[i - 64];
    float o = (xv * cs[t * HD_ + i] + rot * sn[t * HD_ + i]) * 0.08838834764831845f;
    ((unsigned*)qout)[(((size_t)(b * H_ + h) * T_) + t) * HD_ + i] = f2tf32(o);
}

// ---------------- K: RMSNorm + RoPE -> tf32 bits, in place on (B,T,G,HD) ----------------
__global__ void knorm_rope(float* __restrict__ kbuf, const float* __restrict__ w,
                           const float* __restrict__ cs, const float* __restrict__ sn) {
    int t = blockIdx.x;
    int bg = blockIdx.y;
    int b = bg >> 2, g = bg & 3;
    int i = threadIdx.x;

    size_t base = ((size_t)(b * T_ + t) * G_ + g) * HD_;
    float v = kbuf[base + i];

    float ss = v * v;
#pragma unroll
    for (int o = 16; o > 0; o >>= 1) ss += __shfl_xor_sync(0xffffffffu, ss, o);
    __shared__ float warpsum[4];
    __shared__ float normed[HD_];
    if ((i & 31) == 0) warpsum[i >> 5] = ss;
    __syncthreads();
    float tot = warpsum[0] + warpsum[1] + warpsum[2] + warpsum[3];
    float rms = rsqrtf(tot * (1.0f / HD_) + 1e-6f);
    float xv = v * rms * w[i];
    normed[i] = xv;
    __syncthreads();
    float rot = (i < 64) ? -normed[i + 64] : normed[i - 64];
    ((unsigned*)kbuf)[base + i] = f2tf32(xv * cs[t * HD_ + i] + rot * sn[t * HD_ + i]);
}

// ---------------- causal GQA flash attention on tf32 tensor cores ----------------
// BQ=64, BK=64. 8 warps: warp w -> S tile rows (w&3)*16, cols (w>>2)*32;
//                        O tile rows (w&3)*16, d cols (w>>2)*64.
// Pitches: QP/KP=132 (≡4 mod 32), VP=136 (≡8), SP=68 (≡4) — conflict-free for
// the tf32 m16n8k8 fragment lane maps. P split hi/lo tf32 for 2-pass PV.
#define QP 132
#define VP 136
#define SP 68
#define FLASH_SMEM ((64 * QP * 2 + 64 * VP + 64 * SP * 2 + 3 * 64) * 4)

__global__ __launch_bounds__(256, 1) void flash_tc(
        const float* __restrict__ Q, const float* __restrict__ K,
        const float* __restrict__ V, const float* __restrict__ qg,
        float* __restrict__ Oout) {
    extern __shared__ float sm[];
    float* Qs   = sm;               // 64 x QP (tf32 bits)
    float* Ks   = Qs + 64 * QP;     // 64 x QP
    float* Vs   = Ks + 64 * QP;     // 64 x VP
    float* Sh   = Vs + 64 * VP;     // 64 x SP  (raw scores, then P hi tf32 bits)
    float* Sl   = Sh + 64 * SP;     // 64 x SP  (P lo tf32 bits)
    float* rowm = Sl + 64 * SP;
    float* rowl = rowm + 64;
    float* ralp = rowl + 64;

    int qt = gridDim.x - 1 - blockIdx.x;  // heavy tiles first
    int bh = blockIdx.y;
    int b = bh >> 4, h = bh & 15;
    int g = h >> 2;
    int tid = threadIdx.x;
    int w = tid >> 5, lane = tid & 31;
    int m0  = (w & 3) * 16;
    int n0s = (w >> 2) * 32;
    int n0d = (w >> 2) * 64;
    int lr = lane >> 2, lc = lane & 3;

    const float* Qb = Q + (((size_t)(b * H_ + h) * T_) + qt * 64) * HD_;
    const float* Kb = K + ((size_t)b * T_ * G_ + g) * HD_;
    const float* Vb = V + ((size_t)b * T_ * G_ + g) * HD_;

    for (int i = tid; i < 64 * 32; i += 256) {
        int r = i >> 5, c4 = (i & 31) * 4;
        *(float4*)&Qs[r * QP + c4] = *(const float4*)(Qb + r * HD_ + c4);
    }
    if (tid < 64) { rowm[tid] = -3e30f; rowl[tid] = 0.f; }

    float o[8][4];
#pragma unroll
    for (int nf = 0; nf < 8; nf++)
#pragma unroll
        for (int c = 0; c < 4; c++) o[nf][c] = 0.f;
    __syncthreads();

    for (int j = 0; j <= qt; j++) {
        const float* Kt = Kb + (size_t)(j * 64) * (G_ * HD_);
        const float* Vt = Vb + (size_t)(j * 64) * (G_ * HD_);
        for (int i = tid; i < 64 * 32; i += 256) {
            int r = i >> 5, c4 = (i & 31) * 4;
            *(float4*)&Ks[r * QP + c4] = *(const float4*)(Kt + (size_t)r * (G_ * HD_) + c4);
            *(float4*)&Vs[r * VP + c4] = *(const float4*)(Vt + (size_t)r * (G_ * HD_) + c4);
        }
        __syncthreads();

        // ---- S = Q K^T (tf32 MMA) ----
        float s[4][4];
#pragma unroll
        for (int nf = 0; nf < 4; nf++)
#pragma unroll
            for (int c = 0; c < 4; c++) s[nf][c] = 0.f;

#pragma unroll
        for (int ks = 0; ks < 16; ks++) {
            int k0 = ks * 8;
            unsigned a0 = __float_as_uint(Qs[(m0 + lr)     * QP + k0 + lc]);
            unsigned a1 = __float_as_uint(Qs[(m0 + lr + 8) * QP + k0 + lc]);
            unsigned a2 = __float_as_uint(Qs[(m0 + lr)     * QP + k0 + lc + 4]);
            unsigned a3 = __float_as_uint(Qs[(m0 + lr + 8) * QP + k0 + lc + 4]);
#pragma unroll
            for (int nf = 0; nf < 4; nf++) {
                int n = n0s + nf * 8;
                unsigned b0 = __float_as_uint(Ks[(n + lr) * QP + k0 + lc]);
                unsigned b1 = __float_as_uint(Ks[(n + lr) * QP + k0 + lc + 4]);
                mma_tf32(s[nf], a0, a1, a2, a3, b0, b1);
            }
        }

        // store S to smem
#pragma unroll
        for (int nf = 0; nf < 4; nf++) {
            int col = n0s + nf * 8 + lc * 2;
            *(float2*)&Sh[(m0 + lr)     * SP + col] = make_float2(s[nf][0], s[nf][1]);
            *(float2*)&Sh[(m0 + lr + 8) * SP + col] = make_float2(s[nf][2], s[nf][3]);
        }
        __syncthreads();

        // ---- row softmax (64 threads), split P into tf32 hi/lo ----
        if (tid < 64) {
            int rr = tid;
            float* Sr = &Sh[rr * SP];
            float* Lr = &Sl[rr * SP];
            bool diag = (j == qt);
            float m = rowm[rr], mn = m;
#pragma unroll 8
            for (int c = 0; c < 64; c++) {
                float sv = (diag && c > rr) ? -3e30f : Sr[c];
                mn = fmaxf(mn, sv);
            }
            float a = __expf(m - mn);
            float l = rowl[rr] * a;
#pragma unroll 8
            for (int c = 0; c < 64; c++) {
                float sv = (diag && c > rr) ? -3e30f : Sr[c];
                float p = __expf(sv - mn);
                l += p;
                unsigned ph = f2tf32(p);
                float pl = p - __uint_as_float(ph);
                Sr[c] = __uint_as_float(ph);
                Lr[c] = __uint_as_float(f2tf32(pl));
            }
            rowm[rr] = mn; rowl[rr] = l; ralp[rr] = a;
        }
        __syncthreads();

        // rescale O accumulators
        float aL = ralp[m0 + lr], aH = ralp[m0 + 8 + lr];
#pragma unroll
        for (int nf = 0; nf < 8; nf++) {
            o[nf][0] *= aL; o[nf][1] *= aL; o[nf][2] *= aH; o[nf][3] *= aH;
        }

        // ---- O += P V (2-pass: P hi + P lo) ----
#pragma unroll
        for (int ks = 0; ks < 8; ks++) {
            int k0 = ks * 8;
            unsigned h0 = __float_as_uint(Sh[(m0 + lr)     * SP + k0 + lc]);
            unsigned h1 = __float_as_uint(Sh[(m0 + lr + 8) * SP + k0 + lc]);
            unsigned h2 = __float_as_uint(Sh[(m0 + lr)     * SP + k0 + lc + 4]);
            unsigned h3 = __float_as_uint(Sh[(m0 + lr + 8) * SP + k0 + lc + 4]);
            unsigned l0 = __float_as_uint(Sl[(m0 + lr)     * SP + k0 + lc]);
            unsigned l1 = __float_as_uint(Sl[(m0 + lr + 8) * SP + k0 + lc]);
            unsigned l2 = __float_as_uint(Sl[(m0 + lr)     * SP + k0 + lc + 4]);
            unsigned l3 = __float_as_uint(Sl[(m0 + lr + 8) * SP + k0 + lc + 4]);
#pragma unroll
            for (int nf = 0; nf < 8; nf++) {
                int n = n0d + nf * 8;
                unsigned b0 = __float_as_uint(Vs[(k0 + lc)     * VP + n + lr]);
                unsigned b1 = __float_as_uint(Vs[(k0 + lc + 4) * VP + n + lr]);
                mma_tf32(o[nf], h0, h1, h2, h3, b0, b1);
                mma_tf32(o[nf], l0, l1, l2, l3, b0, b1);
            }
        }
        __syncthreads();
    }

    // ---- epilogue: 1/l, sigmoid gate, tf32 rounding ----
#pragma unroll
    for (int half = 0; half < 2; half++) {
        int rr = m0 + half * 8 + lr;
        float linv = 1.0f / rowl[rr];
        int grow = qt * 64 + rr;
        const float* gbase = qg + (((size_t)(b * T_ + grow) * H_ + h) * 2 * HD_) + HD_;
        unsigned* obase = (unsigned*)(Oout + ((size_t)(b * T_ + grow) * (H_ * HD_)) + h * HD_);
#pragma unroll
        for (int nf = 0; nf < 8; nf++) {
            int d = n0d + nf * 8 + lc * 2;
#pragma unroll
            for (int e = 0; e < 2; e++) {
                float gt = gbase[d + e];
                float sg = 1.0f / (1.0f + __expf(-gt));
                float val = o[nf][half * 2 + e] * linv * sg;
                obase[d + e] = f2tf32(val);
            }
        }
    }
}

// ---------------- launch ----------------
extern "C" void kernel_launch(void* const* d_in, const int* in_sizes, int n_in,
                              void* d_out, int out_size) {
    const float* x    = (const float*)d_in[0];
    const float* w_q  = (const float*)d_in[1];
    const float* w_k  = (const float*)d_in[2];
    const float* w_v  = (const float*)d_in[3];
    const float* w_o  = (const float*)d_in[4];
    const float* qnw  = (const float*)d_in[5];
    const float* knw  = (const float*)d_in[6];
    const float* cs   = (const float*)d_in[7];
    const float* sn   = (const float*)d_in[8];
    float* out = (float*)d_out;

    float *qg, *q, *k, *v, *attn, *xt, *wqt, *wkt, *wvt, *wot;
    cudaGetSymbolAddress((void**)&qg,   g_qg);
    cudaGetSymbolAddress((void**)&q,    g_q);
    cudaGetSymbolAddress((void**)&k,    g_k);
    cudaGetSymbolAddress((void**)&v,    g_v);
    cudaGetSymbolAddress((void**)&attn, g_attn);
    cudaGetSymbolAddress((void**)&xt,   g_xt);
    cudaGetSymbolAddress((void**)&wqt,  g_wqt);
    cudaGetSymbolAddress((void**)&wkt,  g_wkt);
    cudaGetSymbolAddress((void**)&wvt,  g_wvt);
    cudaGetSymbolAddress((void**)&wot,  g_wot);

    cudaFuncSetAttribute((const void*)flash_tc,
                         cudaFuncAttributeMaxDynamicSharedMemorySize, FLASH_SMEM);

    const int M = B_ * T_;  // 4096

    // tf32 rounding pre-pass
    {
        int n4;
        n4 = (B_ * T_ * D_) / 4;          cvt_tf32<<<(n4 + 255) / 256, 256>>>(x,   xt,  n4);
        n4 = (D_ * 2 * H_ * HD_) / 4;     cvt_tf32<<<(n4 + 255) / 256, 256>>>(w_q, wqt, n4);
        n4 = (D_ * G_ * HD_) / 4;         cvt_tf32<<<(n4 + 255) / 256, 256>>>(w_k, wkt, n4);
        n4 = (D_ * G_ * HD_) / 4;         cvt_tf32<<<(n4 + 255) / 256, 256>>>(w_v, wvt, n4);
        n4 = (H_ * HD_ * D_) / 4;         cvt_tf32<<<(n4 + 255) / 256, 256>>>(w_o, wot, n4);
    }

    // QKV projections (tensor cores, tf32)
    gemm_tf32<<<dim3((2 * H_ * HD_) / 128, M / 128), 256>>>(xt, wqt, qg, M, 2 * H_ * HD_, D_);
    gemm_tf32<<<dim3((G_ * HD_) / 128,     M / 128), 256>>>(xt, wkt, k,  M, G_ * HD_,     D_);
    gemm_tf32<<<dim3((G_ * HD_) / 128,     M / 128), 256>>>(xt, wvt, v,  M, G_ * HD_,     D_);

    // norms + rope (emit tf32 bits); V -> tf32 bits
    qnorm_rope<<<dim3(T_, B_ * H_), 128>>>(qg, q, qnw, cs, sn);
    knorm_rope<<<dim3(T_, B_ * G_), 128>>>(k, knw, cs, sn);
    {
        int n4 = (B_ * T_ * G_ * HD_) / 4;
        cvt_tf32<<<(n4 + 255) / 256, 256>>>(v, v, n4);
    }

    // attention + gate (tf32 tensor cores; epilogue emits tf32-rounded attn)
    flash_tc<<<dim3(T_ / 64, B_ * H_), 256, FLASH_SMEM>>>(q, k, v, qg, attn);

    // output projection (tensor cores, tf32)
    gemm_tf32<<<dim3(D_ / 128, M / 128), 256>>>(attn, wot, out, M, D_, D_);
}